// round 1
// baseline (speedup 1.0000x reference)
#include <cuda_runtime.h>
#include <cuda_bf16.h>
#include <cstddef>

#define Hd 10
#define Td 20
#define G4 40   // 4*Hd
#define M1 5    // MLP hidden

// ---- fast-but-accurate activations (~2 ulp via MUFU EX2/RCP) ----
__device__ __forceinline__ float fsigmoid(float x) {
    // 1 / (1 + e^-x); __expf -> MUFU.EX2 (+FMUL), __fdividef -> MUFU.RCP (+FMUL)
    return __fdividef(1.0f, 1.0f + __expf(-x));
}
__device__ __forceinline__ float ftanh(float x) {
    // (e^2x - 1)/(e^2x + 1). Arguments here are bounded (|x| < ~45) so no overflow.
    float e = __expf(2.0f * x);
    return __fdividef(e - 1.0f, e + 1.0f);
}

__global__ void __launch_bounds__(256)
lstm_disc_kernel(const float* __restrict__ values,
                 const float* __restrict__ W_ih,   // (40,1)
                 const float* __restrict__ W_hh,   // (40,10)
                 const float* __restrict__ b_ih,   // (40)
                 const float* __restrict__ b_hh,   // (40)
                 const float* __restrict__ W1,     // (5,10)
                 const float* __restrict__ b1,     // (5)
                 const float* __restrict__ W2,     // (1,5)
                 const float* __restrict__ b2,     // (1)
                 float* __restrict__ scores,       // (B,T)
                 int B)
{
    // weights in shared: warp-uniform access -> broadcast, conflict-free
    __shared__ __align__(16) float sWt[Hd][G4];  // W_hh transposed: sWt[k][j] = W_hh[j][k]
    __shared__ __align__(16) float sWx[G4];      // W_ih[:,0]
    __shared__ __align__(16) float sB[G4];       // b_ih + b_hh
    __shared__ __align__(16) float sW1[M1][Hd+2];// padded rows (keep 8B align per row)
    __shared__ float sB1[M1];
    __shared__ float sW2[M1];
    __shared__ float sB2;

    const int tid = threadIdx.x;
    for (int i = tid; i < G4 * Hd; i += blockDim.x) {
        int j = i / Hd, k = i % Hd;
        sWt[k][j] = W_hh[i];
    }
    for (int i = tid; i < G4; i += blockDim.x) {
        sWx[i] = W_ih[i];
        sB[i]  = b_ih[i] + b_hh[i];
    }
    if (tid < M1 * Hd) sW1[tid / Hd][tid % Hd] = W1[tid];
    if (tid < M1) { sB1[tid] = b1[tid]; sW2[tid] = W2[tid]; }
    if (tid == 0) sB2 = b2[0];
    __syncthreads();

    const int b = blockIdx.x * blockDim.x + threadIdx.x;
    if (b >= B) return;

    float h[Hd], c[Hd];
#pragma unroll
    for (int k = 0; k < Hd; k++) { h[k] = 0.0f; c[k] = 0.0f; }

    const float* __restrict__ vrow = values + (size_t)b * Td;
    float* __restrict__ srow = scores + (size_t)b * Td;

#pragma unroll 1
    for (int t = 0; t < Td; t++) {
        // ---- MLP scoring head on current h (pre-update) ----
        float acc = sB2;
#pragma unroll
        for (int j = 0; j < M1; j++) {
            float a = sB1[j];
#pragma unroll
            for (int k = 0; k < Hd; k++) a = fmaf(h[k], sW1[j][k], a);
            a = fmaxf(a, 0.2f * a);           // leaky_relu(0.2)
            acc = fmaf(sW2[j], a, acc);
        }
        srow[t] = fsigmoid(acc);

        // ---- LSTM step ----
        const float x = vrow[t];
        float g[G4];
#pragma unroll
        for (int j = 0; j < G4; j++) g[j] = fmaf(x, sWx[j], sB[j]);
#pragma unroll
        for (int k = 0; k < Hd; k++) {
            const float hk = h[k];
#pragma unroll
            for (int j = 0; j < G4; j++) g[j] = fmaf(hk, sWt[k][j], g[j]);
        }
#pragma unroll
        for (int u = 0; u < Hd; u++) {
            const float ig = fsigmoid(g[u]);
            const float fg = fsigmoid(g[u + 10]);
            const float gg = ftanh(g[u + 20]);
            const float og = fsigmoid(g[u + 30]);
            const float cn = fmaf(fg, c[u], ig * gg);
            c[u] = cn;
            h[u] = og * ftanh(cn);
        }
    }
}

__global__ void copy_masks_kernel(const float4* __restrict__ in,
                                  float4* __restrict__ out, int n4)
{
    int i = blockIdx.x * blockDim.x + threadIdx.x;
    int stride = gridDim.x * blockDim.x;
    for (; i < n4; i += stride) out[i] = in[i];
}

extern "C" void kernel_launch(void* const* d_in, const int* in_sizes, int n_in,
                              void* d_out, int out_size)
{
    const float* values = (const float*)d_in[0];
    const float* masks  = (const float*)d_in[1];
    const float* W_ih   = (const float*)d_in[2];
    const float* W_hh   = (const float*)d_in[3];
    const float* b_ih   = (const float*)d_in[4];
    const float* b_hh   = (const float*)d_in[5];
    const float* W1     = (const float*)d_in[6];
    const float* b1     = (const float*)d_in[7];
    const float* W2     = (const float*)d_in[8];
    const float* b2     = (const float*)d_in[9];
    // d_in[10] = args (0), d_in[11] = direct (0) — constants per setup_inputs

    const int BT = in_sizes[0];          // B*T
    const int B  = BT / Td;
    float* out = (float*)d_out;

    lstm_disc_kernel<<<(B + 255) / 256, 256>>>(
        values, W_ih, W_hh, b_ih, b_hh, W1, b1, W2, b2, out, B);

    // masks passthrough -> second half of the output buffer
    const int n4 = BT / 4;               // BT = 5,242,880 divisible by 4
    copy_masks_kernel<<<(n4 + 255) / 256, 256>>>(
        (const float4*)masks, (float4*)(out + (size_t)BT), n4);
}

// round 2
// speedup vs baseline: 1.2185x; 1.2185x over previous
#include <cuda_runtime.h>
#include <cstddef>

#define Hd 10
#define Td 20
#define G4 40   // 4*Hd
#define M1 5    // MLP hidden

using u64 = unsigned long long;

// ---- f32x2 packed helpers (sm_100+) ----
__device__ __forceinline__ u64 pack2(float lo, float hi) {
    u64 r;
    asm("mov.b64 %0, {%1, %2};" : "=l"(r) : "f"(lo), "f"(hi));
    return r;
}
__device__ __forceinline__ void unpack2(u64 v, float &lo, float &hi) {
    asm("mov.b64 {%0, %1}, %2;" : "=f"(lo), "=f"(hi) : "l"(v));
}
__device__ __forceinline__ void fma2(u64 &d, u64 a, u64 b) {
    asm("fma.rn.f32x2 %0, %1, %2, %0;" : "+l"(d) : "l"(a), "l"(b));
}
__device__ __forceinline__ u64 fma2_3(u64 a, u64 b, u64 c) {
    u64 d;
    asm("fma.rn.f32x2 %0, %1, %2, %3;" : "=l"(d) : "l"(a), "l"(b), "l"(c));
    return d;
}

// ---- activations ----
__device__ __forceinline__ float tanh_fast(float x) {
    float r; asm("tanh.approx.f32 %0, %1;" : "=f"(r) : "f"(x)); return r;
}
__device__ __forceinline__ float sig_fast(float x) {
    return fmaf(tanh_fast(0.5f * x), 0.5f, 0.5f);   // 1 MUFU
}
__device__ __forceinline__ float sig_acc(float x) {  // accurate, for final score
    return __fdividef(1.0f, 1.0f + __expf(-x));
}

__global__ void __launch_bounds__(256)
lstm_disc_kernel(const float* __restrict__ values,
                 const float* __restrict__ masks,
                 const float* __restrict__ W_ih,   // (40,1)
                 const float* __restrict__ W_hh,   // (40,10)
                 const float* __restrict__ b_ih,   // (40)
                 const float* __restrict__ b_hh,   // (40)
                 const float* __restrict__ W1,     // (5,10)
                 const float* __restrict__ b1,     // (5)
                 const float* __restrict__ W2,     // (1,5)
                 const float* __restrict__ b2,     // (1)
                 float* __restrict__ out,          // scores (B,T) then masks (B,T)
                 int B)
{
    // Weight staging in shared; all per-step accesses are warp-uniform broadcast,
    // read as 16B (LDS.128) or 8B (LDS.64) vectors.
    __shared__ __align__(16) float sWt[Hd][G4];   // sWt[k][j] = W_hh[j][k] (row = 160B, 16B-aligned)
    __shared__ __align__(16) float sWx[G4];       // W_ih[:,0]
    __shared__ __align__(16) float sB[G4];        // b_ih + b_hh
    __shared__ __align__(8)  float2 sW1p[M1][5];  // W1 row pairs: (W1[j][2q], W1[j][2q+1])
    __shared__ __align__(8)  float2 sB1p[M1];     // (b1[j], 0)
    __shared__ float sW2[M1];
    __shared__ float sB2;

    const int tid = threadIdx.x;
    for (int i = tid; i < G4 * Hd; i += blockDim.x) {
        int j = i / Hd, k = i % Hd;
        sWt[k][j] = W_hh[i];
    }
    if (tid < G4) {
        sWx[tid] = W_ih[tid];
        sB[tid]  = b_ih[tid] + b_hh[tid];
    }
    if (tid < M1 * 5) {
        int j = tid / 5, q = tid % 5;
        sW1p[j][q] = make_float2(W1[j * Hd + 2 * q], W1[j * Hd + 2 * q + 1]);
    }
    if (tid < M1) { sB1p[tid] = make_float2(b1[tid], 0.0f); sW2[tid] = W2[tid]; }
    if (tid == 0) sB2 = b2[0];
    __syncthreads();

    const int b = blockIdx.x * blockDim.x + threadIdx.x;
    if (b >= B) return;

    float h[Hd], c[Hd];
#pragma unroll
    for (int k = 0; k < Hd; k++) { h[k] = 0.0f; c[k] = 0.0f; }

    const float* __restrict__ vrow = values + (size_t)b * Td;
    float* __restrict__ srow = out + (size_t)b * Td;

#pragma unroll 1
    for (int t = 0; t < Td; t++) {
        // ---- MLP scoring head on current h (pre-update), packed f32x2 ----
        u64 hp[M1];
#pragma unroll
        for (int q = 0; q < M1; q++) hp[q] = pack2(h[2 * q], h[2 * q + 1]);

        float acc = sB2;
#pragma unroll
        for (int j = 0; j < M1; j++) {
            u64 a2 = *reinterpret_cast<const u64*>(&sB1p[j]);
#pragma unroll
            for (int q = 0; q < M1; q++) {
                u64 w = *reinterpret_cast<const u64*>(&sW1p[j][q]);
                fma2(a2, hp[q], w);
            }
            float lo, hi; unpack2(a2, lo, hi);
            float a = lo + hi;
            a = fmaxf(a, 0.2f * a);              // leaky_relu(0.2)
            acc = fmaf(sW2[j], a, acc);
        }
        srow[t] = sig_acc(acc);

        // ---- LSTM gates: g = x*Wx + b + h @ Whh^T, packed f32x2 ----
        const float x = vrow[t];
        const u64 x2 = pack2(x, x);
        u64 g2[G4 / 2];
        const ulonglong2* __restrict__ wxr = reinterpret_cast<const ulonglong2*>(sWx);
        const ulonglong2* __restrict__ bbr = reinterpret_cast<const ulonglong2*>(sB);
#pragma unroll
        for (int q = 0; q < 10; q++) {
            ulonglong2 w = wxr[q];               // LDS.128 -> 2 f32x2
            ulonglong2 bb = bbr[q];
            g2[2 * q]     = fma2_3(x2, w.x, bb.x);
            g2[2 * q + 1] = fma2_3(x2, w.y, bb.y);
        }
#pragma unroll
        for (int k = 0; k < Hd; k++) {
            const u64 hk2 = pack2(h[k], h[k]);
            const ulonglong2* __restrict__ row = reinterpret_cast<const ulonglong2*>(sWt[k]);
#pragma unroll
            for (int q = 0; q < 10; q++) {
                ulonglong2 w = row[q];           // LDS.128 -> 2 f32x2 -> 4 FMAs
                fma2(g2[2 * q],     hk2, w.x);
                fma2(g2[2 * q + 1], hk2, w.y);
            }
        }

        // ---- activations + state update, pairwise (no gf[] spill array) ----
        // gate layout: lanes u in [0,10): i=g[u], f=g[u+10], g=g[u+20], o=g[u+30]
        // g2[p] holds lanes (2p, 2p+1) of gate block p/5.
#pragma unroll
        for (int p = 0; p < 5; p++) {
            float i0, i1, f0, f1, gg0, gg1, o0, o1;
            unpack2(g2[p],      i0,  i1);
            unpack2(g2[p + 5],  f0,  f1);
            unpack2(g2[p + 10], gg0, gg1);
            unpack2(g2[p + 15], o0,  o1);
            const int u0 = 2 * p, u1 = 2 * p + 1;

            float cn0 = fmaf(sig_fast(f0), c[u0], sig_fast(i0) * tanh_fast(gg0));
            float cn1 = fmaf(sig_fast(f1), c[u1], sig_fast(i1) * tanh_fast(gg1));
            c[u0] = cn0; c[u1] = cn1;
            h[u0] = sig_fast(o0) * tanh_fast(cn0);
            h[u1] = sig_fast(o1) * tanh_fast(cn1);
        }
    }

    // ---- masks passthrough (fused; 5x float4 per thread) ----
    const float4* __restrict__ mrow = reinterpret_cast<const float4*>(masks + (size_t)b * Td);
    float4* __restrict__ morow = reinterpret_cast<float4*>(out + (size_t)B * Td + (size_t)b * Td);
#pragma unroll
    for (int q = 0; q < Td / 4; q++) morow[q] = mrow[q];
}

extern "C" void kernel_launch(void* const* d_in, const int* in_sizes, int n_in,
                              void* d_out, int out_size)
{
    const float* values = (const float*)d_in[0];
    const float* masks  = (const float*)d_in[1];
    const float* W_ih   = (const float*)d_in[2];
    const float* W_hh   = (const float*)d_in[3];
    const float* b_ih   = (const float*)d_in[4];
    const float* b_hh   = (const float*)d_in[5];
    const float* W1     = (const float*)d_in[6];
    const float* b1     = (const float*)d_in[7];
    const float* W2     = (const float*)d_in[8];
    const float* b2     = (const float*)d_in[9];
    // d_in[10] = args (0), d_in[11] = direct (0) — constants per setup_inputs

    const int BT = in_sizes[0];          // B*T
    const int B  = BT / Td;
    float* out = (float*)d_out;

    lstm_disc_kernel<<<(B + 255) / 256, 256>>>(
        values, masks, W_ih, W_hh, b_ih, b_hh, W1, b1, W2, b2, out, B);
}